// round 14
// baseline (speedup 1.0000x reference)
#include <cuda_runtime.h>
#include <math.h>
#include <stdint.h>

#define B 4
#define T 64
#define F 64
#define U 64
#define M 64
#define TF (T*F)
#define NTH 1024

// Accurate tanh for value paths (h, ms): abs err ~1e-7.
__device__ __forceinline__ float fast_tanh(float x) {
    float e = __expf(2.0f * x);
    return 1.0f - __fdividef(2.0f, e + 1.0f);
}
// Single-MUFU f32 tanh for the argmax-only score path (proven argmax-safe).
__device__ __forceinline__ float tanh_mufu(float x) {
    float y; asm("tanh.approx.f32 %0, %1;" : "=f"(y) : "f"(x)); return y;
}
__device__ __forceinline__ uint32_t smem_u32(const void* p) {
    uint32_t a;
    asm("{ .reg .u64 t; cvta.to.shared.u64 t, %1; cvt.u32.u64 %0, t; }" : "=r"(a) : "l"(p));
    return a;
}
__device__ __forceinline__ void stc_f32(uint32_t saddr, int rank, float v) {
    uint32_t rr;
    asm volatile("mapa.shared::cluster.u32 %0, %1, %2;" : "=r"(rr) : "r"(saddr), "r"(rank));
    asm volatile("st.shared::cluster.f32 [%0], %1;" :: "r"(rr), "f"(v) : "memory");
}
__device__ __forceinline__ void stc_s32(uint32_t saddr, int rank, int v) {
    uint32_t rr;
    asm volatile("mapa.shared::cluster.u32 %0, %1, %2;" : "=r"(rr) : "r"(saddr), "r"(rank));
    asm volatile("st.shared::cluster.u32 [%0], %1;" :: "r"(rr), "r"(v) : "memory");
}
__device__ __forceinline__ void stc_u64(uint32_t saddr, int rank, unsigned long long v) {
    uint32_t rr;
    asm volatile("mapa.shared::cluster.u32 %0, %1, %2;" : "=r"(rr) : "r"(saddr), "r"(rank));
    asm volatile("st.shared::cluster.u64 [%0], %1;" :: "r"(rr), "l"(v) : "memory");
}
__device__ __forceinline__ void cluster_arrive() {
    asm volatile("barrier.cluster.arrive.aligned;" ::: "memory");
}
__device__ __forceinline__ void cluster_wait() {
    asm volatile("barrier.cluster.wait.aligned;" ::: "memory");
}

// =====================================================================
// Cluster of CPB_ CTAs per batch, 32 warps per CTA.
// RPC_ = T/CPB_ rows per CTA; each row owned by WPR = 32/RPC_ warps that
// split the 64-deep reduction of every phase-1 stage into CHK chains.
// =====================================================================
template<int CPB_>
__global__ void __launch_bounds__(NTH)
fused_all(const float* __restrict__ inp,
          const float* __restrict__ Wk,
          const float* __restrict__ bk,
          const float* __restrict__ Wv,
          const float* __restrict__ bv,
          const float* __restrict__ w_s,
          const float* __restrict__ mem_keys,
          const float* __restrict__ mem_vals,
          float* __restrict__ d_out) {
    constexpr int RPC_ = T / CPB_;     // rows per CTA (8 or 4)
    constexpr int WPR  = 32 / RPC_;    // warps per row (4 or 8)
    constexpr int CHK  = 64 / WPR;     // reduction chunk (16 or 8)
    constexpr int NF4  = RPC_ * F / 4; // float4s in this CTA's ms slice

    const int b    = blockIdx.x / CPB_;
    const int r    = blockIdx.x % CPB_;
    const int tid  = threadIdx.x;
    const int w    = tid >> 5;
    const int lane = tid & 31;
    const int tl   = w / WPR;          // row owned by this warp group
    const int sub  = w % WPR;

    __shared__ __align__(16) float s_in[RPC_][F];
    __shared__ float s_hp[WPR][RPC_][U];
    __shared__ float s_h [RPC_][U];
    __shared__ float s_op[WPR][RPC_][F];
    __shared__ float s_o [RPC_][F];
    __shared__ float s_scp[WPR][RPC_][F];
    __shared__ __align__(16) float s_ms[RPC_*F];
    __shared__ unsigned long long s_candloc[F];
    __shared__ unsigned long long s_cand[CPB_][F];
    __shared__ int   s_idxt[T];
    __shared__ float s_lp[CPB_][M];
    __shared__ float s_ws[F];
    __shared__ float s_attn[M];
    __shared__ float s_tpart[16][F];
    __shared__ float s_amax[RPC_], s_amin[RPC_];
    __shared__ float s_wmm[2];
    __shared__ float s_imp;

    if (tid < F) s_ws[tid] = w_s[tid];
    const float wlast = __ldg(w_s + 63);

    // ---- stage inputs ----
    if (tid < RPC_*F)
        s_in[tid >> 6][tid & 63] = inp[(b*T + r*RPC_)*F + tid];
    __syncthreads();

    // ---- h partials: group splits f; u0 = 2*lane ----
    {
        const int fbase = sub*CHK;
        const int u0 = 2*lane;
        float a0 = 0.f, a1 = 0.f;
        #pragma unroll
        for (int f = 0; f < CHK; ++f) {
            float2 kk = *(const float2*)(Wk + (fbase + f)*U + u0);
            float x = s_in[tl][fbase + f];
            a0 = fmaf(x, kk.x, a0);
            a1 = fmaf(x, kk.y, a1);
        }
        s_hp[sub][tl][u0] = a0; s_hp[sub][tl][u0+1] = a1;
    }
    __syncthreads();
    if (tid < RPC_*U) {
        const int t = tid >> 6, u = tid & 63;
        float s = __ldg(bk + u);
        #pragma unroll
        for (int q = 0; q < WPR; ++q) s += s_hp[q][t][u];
        s_h[t][u] = fast_tanh(s);
    }
    __syncthreads();

    // ---- output partials: group splits u; f0 = 2*lane ----
    {
        const int ubase = sub*CHK;
        const int f0 = 2*lane;
        float o0 = 0.f, o1 = 0.f;
        #pragma unroll
        for (int u = 0; u < CHK; ++u) {
            float2 vv = *(const float2*)(Wv + (ubase + u)*F + f0);
            float hv = s_h[tl][ubase + u];
            o0 = fmaf(hv, vv.x, o0);
            o1 = fmaf(hv, vv.y, o1);
        }
        s_op[sub][tl][f0] = o0; s_op[sub][tl][f0+1] = o1;
    }
    __syncthreads();
    if (tid < RPC_*F) {
        const int t = tid >> 6, f = tid & 63;
        float o = __ldg(bv + f);
        #pragma unroll
        for (int q = 0; q < WPR; ++q) o += s_op[q][t][f];
        s_o[t][f] = o;
        d_out[2*B*T + (b*T + r*RPC_)*F + tid] = o;
    }
    __syncthreads();

    // ---- score partials: group splits u; f0 = 2*lane ----
    {
        const int ubase = sub*CHK;
        const int f0 = 2*lane;
        const float c0 = s_o[tl][f0] * wlast, c1 = s_o[tl][f0+1] * wlast;
        float sc0 = 0.f, sc1 = 0.f;
        #pragma unroll
        for (int u = 0; u < CHK; ++u) {
            float hv = s_h[tl][ubase + u];
            sc0 += tanh_mufu(hv * c0);
            sc1 += tanh_mufu(hv * c1);
        }
        s_scp[sub][tl][f0] = sc0; s_scp[sub][tl][f0+1] = sc1;
    }
    __syncthreads();

    // ---- idx_t (warps 0..RPC_-1, row = w): fused partial-sum + argmax ----
    if (w < RPC_) {
        const int f0 = 2*lane;
        float sc0 = 0.f, sc1 = 0.f;
        #pragma unroll
        for (int q = 0; q < WPR; ++q) {
            sc0 += s_scp[q][w][f0];
            sc1 += s_scp[q][w][f0+1];
        }
        float bvv = sc0; int bf = f0;
        if (sc1 > bvv) { bvv = sc1; bf = f0 + 1; }
        #pragma unroll
        for (int o = 16; o; o >>= 1) {
            float ov = __shfl_xor_sync(0xffffffffu, bvv, o);
            int   of = __shfl_xor_sync(0xffffffffu, bf,  o);
            if (ov > bvv || (ov == bvv && of < bf)) { bvv = ov; bf = of; }
        }
        if (lane < CPB_)
            stc_s32(smem_u32(&s_idxt[r*RPC_ + w]), lane, bf);
    }
    // ---- per-f column-max candidate (warps RPC_, RPC_+1), same sum order ----
    else if (w < RPC_ + 2) {
        const int f = (w - RPC_)*32 + lane;
        float best = -INFINITY; int bt = 0;
        #pragma unroll
        for (int t = 0; t < RPC_; ++t) {
            float v = 0.f;
            #pragma unroll
            for (int q = 0; q < WPR; ++q) v += s_scp[q][t][f];
            if (v > best) { best = v; bt = t; }
        }
        s_candloc[f] =
            ((unsigned long long)__float_as_uint(best) << 32) | (unsigned)(r*RPC_ + bt);
    }
    __syncthreads();

    // ---- push candidates: 1 (f, rank) pair per thread ----
    if (tid < F*CPB_)
        stc_u64(smem_u32(&s_cand[r][tid & 63]), tid >> 6, s_candloc[tid & 63]);
    cluster_arrive();
    cluster_wait();   // A: idx_t + candidates visible everywhere

    // ---- wmax/wmin (warp 0) ----
    if (w == 0) {
        float wv[2];
        #pragma unroll
        for (int hh = 0; hh < 2; ++hh) {
            const int f = lane + hh*32;
            unsigned long long c = s_cand[0][f];
            float best = __uint_as_float((unsigned)(c >> 32));
            int   bt   = (int)(c & 0xffffffffu);
            #pragma unroll
            for (int rr = 1; rr < CPB_; ++rr) {
                unsigned long long cc = s_cand[rr][f];
                float v = __uint_as_float((unsigned)(cc >> 32));
                if (v > best) { best = v; bt = (int)(cc & 0xffffffffu); }
            }
            wv[hh] = s_ws[bt];
        }
        float mx = fmaxf(wv[0], wv[1]), mn = fminf(wv[0], wv[1]);
        #pragma unroll
        for (int o = 16; o; o >>= 1) {
            mx = fmaxf(mx, __shfl_xor_sync(0xffffffffu, mx, o));
            mn = fminf(mn, __shfl_xor_sync(0xffffffffu, mn, o));
        }
        if (lane == 0) { s_wmm[0] = mx; s_wmm[1] = mn; }
    }
    // ---- amax/amin: warps 16..16+RPC_-1, row = w-16 ----
    else if (w >= 16 && w < 16 + RPC_) {
        const int t = w - 16;
        float v0 = s_h[t][s_idxt[lane]];
        float v1 = s_h[t][s_idxt[lane + 32]];
        float mx = fmaxf(v0, v1), mn = fminf(v0, v1);
        #pragma unroll
        for (int o = 16; o; o >>= 1) {
            mx = fmaxf(mx, __shfl_xor_sync(0xffffffffu, mx, o));
            mn = fminf(mn, __shfl_xor_sync(0xffffffffu, mn, o));
        }
        if (lane == 0) { s_amax[t] = mx; s_amin[t] = mn; }
    }
    __syncthreads();

    // ---- ms ----
    if (tid < RPC_*F) {
        const int t = tid >> 6;
        const float c   = s_o[t][tid & 63];
        const float wmax = s_wmm[0], wmin = s_wmm[1];
        const float amx = s_amax[t], amn = s_amin[t];
        float m = fmaxf(fmaxf(amx*wmax*c, amx*wmin*c),
                        fmaxf(amn*wmax*c, amn*wmin*c));
        s_ms[tid] = fast_tanh(m);
    }
    __syncthreads();

    // ---- logit partials: 32 warps, 2 m each ----
    {
        const float4* __restrict__ ms4 = (const float4*)s_ms;
        #pragma unroll
        for (int k = 0; k < 2; ++k) {
            const int m = w*2 + k;
            const float4* __restrict__ key4 =
                (const float4*)(mem_keys + m*TF + r*(RPC_*F));
            float p0 = 0.f, p1 = 0.f, p2 = 0.f, p3 = 0.f;
            #pragma unroll
            for (int c = 0; c < NF4/32; ++c) {
                float4 kk = key4[c*32 + lane];
                float4 mm = ms4[c*32 + lane];
                p0 = fmaf(kk.x, mm.x, p0);
                p1 = fmaf(kk.y, mm.y, p1);
                p2 = fmaf(kk.z, mm.z, p2);
                p3 = fmaf(kk.w, mm.w, p3);
            }
            float acc = (p0 + p1) + (p2 + p3);
            #pragma unroll
            for (int o = 16; o; o >>= 1)
                acc += __shfl_xor_sync(0xffffffffu, acc, o);
            if (lane < CPB_)
                stc_f32(smem_u32(&s_lp[r][m]), lane, acc);
        }
    }
    cluster_arrive();

    // ---- window B: prefetch mem_vals rows this thread needs ----
    float rv[4];
    {
        const int f = tid & 63, q = tid >> 6;
        #pragma unroll
        for (int k = 0; k < 4; ++k)
            rv[k] = __ldg(mem_vals + (q*4 + k)*F + f);
    }
    cluster_wait();   // B: all logit partials visible everywhere

    // ---- softmax / importance (single warp) ----
    if (w == 0) {
        float l0 = 0.f, l1 = 0.f;
        #pragma unroll
        for (int rr = 0; rr < CPB_; ++rr) {
            l0 += s_lp[rr][lane];
            l1 += s_lp[rr][lane + 32];
        }
        float mx = fmaxf(l0, l1);
        #pragma unroll
        for (int o = 16; o; o >>= 1)
            mx = fmaxf(mx, __shfl_xor_sync(0xffffffffu, mx, o));
        float e0 = __expf(l0 - mx), e1 = __expf(l1 - mx);
        float s = e0 + e1;
        #pragma unroll
        for (int o = 16; o; o >>= 1)
            s += __shfl_xor_sync(0xffffffffu, s, o);
        float inv = 1.0f / s;
        s_attn[lane]      = e0 * inv;
        s_attn[lane + 32] = e1 * inv;
        if (lane == 0) s_imp = inv;   // max(attn) = exp(0)/sum
    }
    __syncthreads();

    // ---- targets partials: 1024 threads, 4 m each (prefetched) ----
    {
        const int f = tid & 63, q = tid >> 6;
        float acc = 0.f;
        #pragma unroll
        for (int k = 0; k < 4; ++k)
            acc = fmaf(s_attn[q*4 + k], rv[k], acc);
        s_tpart[q][f] = acc;
    }
    __syncthreads();

    // ---- dist + importances: warps 0..RPC_-1, row = w ----
    if (w < RPC_) {
        float tg0 = 0.f, tg1 = 0.f;
        #pragma unroll
        for (int q = 0; q < 16; ++q) {
            tg0 += s_tpart[q][lane];
            tg1 += s_tpart[q][lane + 32];
        }
        float d0 = s_in[w][lane]      - tg0;
        float d1 = s_in[w][lane + 32] - tg1;
        float a2 = d0*d0 + d1*d1;
        #pragma unroll
        for (int o = 16; o; o >>= 1)
            a2 += __shfl_xor_sync(0xffffffffu, a2, o);
        if (lane == 0) {
            float nrm = sqrtf(a2);
            float hs  = fminf(fmaxf(0.2f*nrm + 0.5f, 0.f), 1.f);
            d_out[b*T + r*RPC_ + w]       = 0.5f - hs;
            d_out[B*T + b*T + r*RPC_ + w] = s_imp;
        }
    }
}

// =====================================================================
extern "C" void kernel_launch(void* const* d_in, const int* in_sizes, int n_in,
                              void* d_out, int out_size) {
    const float* inp      = (const float*)d_in[0];
    const float* Wk       = (const float*)d_in[1];
    const float* bk       = (const float*)d_in[2];
    const float* Wv       = (const float*)d_in[3];
    const float* bv       = (const float*)d_in[4];
    const float* w_s      = (const float*)d_in[5];
    const float* mem_keys = (const float*)d_in[6];
    const float* mem_vals = (const float*)d_in[7];
    float* out = (float*)d_out;

    cudaLaunchAttribute attr[1];
    attr[0].id = cudaLaunchAttributeClusterDimension;

    // probe: can we run a 16-CTA cluster for this kernel?
    cudaFuncSetAttribute(fused_all<16>,
                         cudaFuncAttributeNonPortableClusterSizeAllowed, 1);
    cudaLaunchConfig_t probe = {};
    probe.gridDim  = dim3(B*16, 1, 1);
    probe.blockDim = dim3(NTH, 1, 1);
    int maxC = 0;
    cudaError_t pe = cudaOccupancyMaxPotentialClusterSize(&maxC, fused_all<16>, &probe);
    (void)cudaGetLastError();   // clear any sticky probe error

    cudaLaunchConfig_t cfg = {};
    cfg.blockDim = dim3(NTH, 1, 1);
    cfg.attrs = attr;
    cfg.numAttrs = 1;

    if (pe == cudaSuccess && maxC >= 16) {
        cfg.gridDim = dim3(B*16, 1, 1);
        attr[0].val.clusterDim = {16, 1, 1};
        cudaLaunchKernelEx(&cfg, fused_all<16>,
                           inp, Wk, bk, Wv, bv, w_s, mem_keys, mem_vals, out);
    } else {
        cfg.gridDim = dim3(B*8, 1, 1);
        attr[0].val.clusterDim = {8, 1, 1};
        cudaLaunchKernelEx(&cfg, fused_all<8>,
                           inp, Wk, bk, Wv, bv, w_s, mem_keys, mem_vals, out);
    }
}